// round 1
// baseline (speedup 1.0000x reference)
#include <cuda_runtime.h>
#include <cuda_bf16.h>
#include <math.h>

// Problem constants
#define BATCH     2
#define SEQ       2048
#define DMODEL    2048
#define NHEADS    16
#define DK        128
#define RANK      8
#define MTOT      (BATCH * SEQ)          // 4096
#define LORA_SCALING 2.0f
#define SM_SCALE  0.08838834764831845f   // 1/sqrt(128)

// ---------------------------------------------------------------------------
// Scratch buffers (static __device__ globals; no allocation allowed)
// ---------------------------------------------------------------------------
__device__ float g_t_qkv[MTOT * 24];                       // x@Aq^T | x@Ak^T | x@Av^T
__device__ float g_t_o[MTOT * 8];                          // ctx@Ao^T
__device__ float g_q[BATCH * NHEADS * SEQ * DK];           // head-major [b][h][s][d]
__device__ float g_k[BATCH * NHEADS * SEQ * DK];
__device__ float g_v[BATCH * NHEADS * SEQ * DK];
__device__ float g_ctx[MTOT * DMODEL];                     // token-major [b*S+s][2048]

// ---------------------------------------------------------------------------
// Kernel 1: LoRA intermediate  T[m][mat*8+r] = sum_k X[m][k] * A_mat[r][k]
// One block per row m, 256 threads.
// ---------------------------------------------------------------------------
template <int NMAT>
__global__ void __launch_bounds__(256)
lora_t_kernel(const float* __restrict__ X,
              const float* __restrict__ A0,
              const float* __restrict__ A1,
              const float* __restrict__ A2,
              float* __restrict__ T, int tstride)
{
    const int m = blockIdx.x;
    const int tid = threadIdx.x;
    const float* Amats[3] = {A0, A1, A2};

    float acc[NMAT * 8];
#pragma unroll
    for (int i = 0; i < NMAT * 8; i++) acc[i] = 0.0f;

    const float* xr = X + (size_t)m * DMODEL;
    for (int k = tid; k < DMODEL; k += 256) {
        float xv = xr[k];
#pragma unroll
        for (int mt = 0; mt < NMAT; mt++) {
            const float* Ap = Amats[mt];
#pragma unroll
            for (int r = 0; r < 8; r++)
                acc[mt * 8 + r] += xv * Ap[r * DMODEL + k];
        }
    }

    __shared__ float red[256];
#pragma unroll
    for (int o = 0; o < NMAT * 8; o++) {
        red[tid] = acc[o];
        __syncthreads();
        for (int s = 128; s > 0; s >>= 1) {
            if (tid < s) red[tid] += red[tid + s];
            __syncthreads();
        }
        if (tid == 0) T[(size_t)m * tstride + o] = red[0];
        __syncthreads();
    }
}

// ---------------------------------------------------------------------------
// Kernel 2: GEMM + LoRA/bias epilogue
//   Y[m][n] = sum_k X[m][k]*W[n][k] + bias[n] + 2 * sum_r T[m][r]*Bm[n][r]
// 128x128x16 tile, 256 threads, 8x8 micro-tile.
// MODE 0: write row-major MxN.  MODE 1: write head-major [b][h][s][d].
// ---------------------------------------------------------------------------
#define AS_STRIDE 132

template <int MODE>
__global__ void __launch_bounds__(256)
gemm_lora_kernel(const float* __restrict__ X,    // M x 2048
                 const float* __restrict__ W,    // 2048 x 2048 (row = n)
                 const float* __restrict__ bias, // 2048
                 const float* __restrict__ T,    // M x tstride
                 const float* __restrict__ Bm,   // 2048 x 8
                 float* __restrict__ Yout,
                 int tstride, int toff)
{
    __shared__ float As[16 * AS_STRIDE];
    __shared__ float Bs[16 * AS_STRIDE];

    const int tid = threadIdx.x;
    const int ty = tid >> 4;          // 0..15
    const int tx = tid & 15;          // 0..15
    const int m0 = blockIdx.y * 128;
    const int n0 = blockIdx.x * 128;

    const float* Xb = X + (size_t)m0 * DMODEL;
    const float* Wb = W + (size_t)n0 * DMODEL;

    float acc[8][8];
#pragma unroll
    for (int i = 0; i < 8; i++)
#pragma unroll
        for (int j = 0; j < 8; j++) acc[i][j] = 0.0f;

    for (int kt = 0; kt < DMODEL; kt += 16) {
#pragma unroll
        for (int w = 0; w < 2; w++) {
            int lin = tid + w * 256;
            int row = lin >> 2;
            int c4  = lin & 3;
            float4 xv = *(const float4*)&Xb[(size_t)row * DMODEL + kt + c4 * 4];
            As[(c4 * 4 + 0) * AS_STRIDE + row] = xv.x;
            As[(c4 * 4 + 1) * AS_STRIDE + row] = xv.y;
            As[(c4 * 4 + 2) * AS_STRIDE + row] = xv.z;
            As[(c4 * 4 + 3) * AS_STRIDE + row] = xv.w;
            float4 wv = *(const float4*)&Wb[(size_t)row * DMODEL + kt + c4 * 4];
            Bs[(c4 * 4 + 0) * AS_STRIDE + row] = wv.x;
            Bs[(c4 * 4 + 1) * AS_STRIDE + row] = wv.y;
            Bs[(c4 * 4 + 2) * AS_STRIDE + row] = wv.z;
            Bs[(c4 * 4 + 3) * AS_STRIDE + row] = wv.w;
        }
        __syncthreads();

#pragma unroll
        for (int k = 0; k < 16; k++) {
            float4 a0 = *(const float4*)&As[k * AS_STRIDE + ty * 8];
            float4 a1 = *(const float4*)&As[k * AS_STRIDE + ty * 8 + 4];
            float4 b0 = *(const float4*)&Bs[k * AS_STRIDE + tx * 8];
            float4 b1 = *(const float4*)&Bs[k * AS_STRIDE + tx * 8 + 4];
            float ra[8] = {a0.x, a0.y, a0.z, a0.w, a1.x, a1.y, a1.z, a1.w};
            float rb[8] = {b0.x, b0.y, b0.z, b0.w, b1.x, b1.y, b1.z, b1.w};
#pragma unroll
            for (int i = 0; i < 8; i++)
#pragma unroll
                for (int j = 0; j < 8; j++)
                    acc[i][j] += ra[i] * rb[j];
        }
        __syncthreads();
    }

    // Epilogue: stage T tile and Bm tile in shared (reuse As/Bs)
    float* sT = As;   // 128 x 8
    float* sB = Bs;   // 128 x 8
    {
        int row = tid >> 1;
        int half = tid & 1;
        float4 tv = *(const float4*)&T[(size_t)(m0 + row) * tstride + toff + half * 4];
        *(float4*)&sT[row * 8 + half * 4] = tv;
        float4 bv = *(const float4*)&Bm[(size_t)(n0 + row) * 8 + half * 4];
        *(float4*)&sB[row * 8 + half * 4] = bv;
    }
    __syncthreads();

#pragma unroll
    for (int j = 0; j < 8; j++) {
        int n = n0 + tx * 8 + j;
        float bn = bias[n];
        const float* br = &sB[(tx * 8 + j) * 8];
#pragma unroll
        for (int i = 0; i < 8; i++) {
            int m = m0 + ty * 8 + i;
            const float* tr = &sT[(ty * 8 + i) * 8];
            float dot = 0.0f;
#pragma unroll
            for (int r = 0; r < 8; r++) dot += tr[r] * br[r];
            float y = acc[i][j] + bn + LORA_SCALING * dot;
            if (MODE == 0) {
                Yout[(size_t)m * DMODEL + n] = y;
            } else {
                int b = m >> 11, s = m & 2047;
                int h = n >> 7,  d = n & 127;
                Yout[((((size_t)b * NHEADS + h) * SEQ + s) << 7) + d] = y;
            }
        }
    }
}

// ---------------------------------------------------------------------------
// Kernel 3: fused flash attention (fp32, non-causal)
// Block: 64 queries of one (b,h); 256 threads; loop over 64-wide KV tiles.
// Shared: Q^T[128][68], KV (K^T[128][68] or V[64][132]), P[64][68], row stats.
// ---------------------------------------------------------------------------
#define QK_STRIDE 68
#define V_STRIDE  132
#define FLASH_SMEM_FLOATS (128*QK_STRIDE + 128*QK_STRIDE + 64*QK_STRIDE + 192)
#define FLASH_SMEM_BYTES  (FLASH_SMEM_FLOATS * 4)

__global__ void __launch_bounds__(256)
flash_kernel(const float* __restrict__ Q,
             const float* __restrict__ K,
             const float* __restrict__ V,
             float* __restrict__ CTX)
{
    extern __shared__ float sm[];
    float* Qst    = sm;                        // [128][68]  (k-major)
    float* KV     = sm + 128 * QK_STRIDE;      // K^T [128][68] then V [64][132]
    float* Ps     = KV + 128 * QK_STRIDE;      // [64][68]
    float* row_m  = Ps + 64 * QK_STRIDE;
    float* row_l  = row_m + 64;
    float* row_sc = row_l + 64;

    const int tid = threadIdx.x;
    const int ty = tid >> 4;   // 0..15
    const int tx = tid & 15;   // 0..15
    const int bh = blockIdx.y;
    const int q0 = blockIdx.x * 64;

    const float* Qg = Q + ((size_t)bh * SEQ + q0) * DK;
    const float* Kg = K + (size_t)bh * SEQ * DK;
    const float* Vg = V + (size_t)bh * SEQ * DK;

    // Load Q tile transposed: Qst[d][m]
#pragma unroll
    for (int w = 0; w < 8; w++) {
        int lin = tid + w * 256;
        int row = lin >> 5;     // 0..63
        int c4  = lin & 31;     // 0..31
        float4 v = *(const float4*)&Qg[(size_t)row * DK + c4 * 4];
        Qst[(c4 * 4 + 0) * QK_STRIDE + row] = v.x;
        Qst[(c4 * 4 + 1) * QK_STRIDE + row] = v.y;
        Qst[(c4 * 4 + 2) * QK_STRIDE + row] = v.z;
        Qst[(c4 * 4 + 3) * QK_STRIDE + row] = v.w;
    }
    if (tid < 64) { row_m[tid] = -INFINITY; row_l[tid] = 0.0f; }

    float acc[4][8];
#pragma unroll
    for (int i = 0; i < 4; i++)
#pragma unroll
        for (int d = 0; d < 8; d++) acc[i][d] = 0.0f;

    for (int j0 = 0; j0 < SEQ; j0 += 64) {
        __syncthreads();   // previous iteration done reading KV / Ps
        // Load K tile transposed: KV[d][n]
#pragma unroll
        for (int w = 0; w < 8; w++) {
            int lin = tid + w * 256;
            int row = lin >> 5;
            int c4  = lin & 31;
            float4 v = *(const float4*)&Kg[(size_t)(j0 + row) * DK + c4 * 4];
            KV[(c4 * 4 + 0) * QK_STRIDE + row] = v.x;
            KV[(c4 * 4 + 1) * QK_STRIDE + row] = v.y;
            KV[(c4 * 4 + 2) * QK_STRIDE + row] = v.z;
            KV[(c4 * 4 + 3) * QK_STRIDE + row] = v.w;
        }
        __syncthreads();

        // Scores: 64x64 = Q(64x128) @ K^T
        float sc[4][4];
#pragma unroll
        for (int i = 0; i < 4; i++)
#pragma unroll
            for (int j = 0; j < 4; j++) sc[i][j] = 0.0f;

#pragma unroll 4
        for (int k = 0; k < DK; k++) {
            float4 qv = *(const float4*)&Qst[k * QK_STRIDE + ty * 4];
            float4 kv = *(const float4*)&KV[k * QK_STRIDE + tx * 4];
            float rq[4] = {qv.x, qv.y, qv.z, qv.w};
            float rk[4] = {kv.x, kv.y, kv.z, kv.w};
#pragma unroll
            for (int i = 0; i < 4; i++)
#pragma unroll
                for (int j = 0; j < 4; j++)
                    sc[i][j] += rq[i] * rk[j];
        }
#pragma unroll
        for (int i = 0; i < 4; i++) {
            float4 ov = make_float4(sc[i][0] * SM_SCALE, sc[i][1] * SM_SCALE,
                                    sc[i][2] * SM_SCALE, sc[i][3] * SM_SCALE);
            *(float4*)&Ps[(ty * 4 + i) * QK_STRIDE + tx * 4] = ov;
        }
        __syncthreads();

        // Online softmax: 4 threads per row, 16 cols each
        {
            int row = tid >> 2;
            int q   = tid & 3;
            float* pr = &Ps[row * QK_STRIDE + q * 16];
            float mx = -INFINITY;
#pragma unroll
            for (int c = 0; c < 16; c++) mx = fmaxf(mx, pr[c]);
            mx = fmaxf(mx, __shfl_xor_sync(0xffffffffu, mx, 1));
            mx = fmaxf(mx, __shfl_xor_sync(0xffffffffu, mx, 2));
            float mold = row_m[row];
            float mnew = fmaxf(mold, mx);
            float scl  = __expf(mold - mnew);
            float ls = 0.0f;
#pragma unroll
            for (int c = 0; c < 16; c++) {
                float e = __expf(pr[c] - mnew);
                pr[c] = e;
                ls += e;
            }
            ls += __shfl_xor_sync(0xffffffffu, ls, 1);
            ls += __shfl_xor_sync(0xffffffffu, ls, 2);
            if (q == 0) {
                row_l[row] = row_l[row] * scl + ls;
                row_m[row] = mnew;
                row_sc[row] = scl;
            }
        }
        __syncthreads();

        // Rescale running context
#pragma unroll
        for (int i = 0; i < 4; i++) {
            float f = row_sc[ty * 4 + i];
#pragma unroll
            for (int d = 0; d < 8; d++) acc[i][d] *= f;
        }

        // Load V tile (row-major) into KV
#pragma unroll
        for (int w = 0; w < 8; w++) {
            int lin = tid + w * 256;
            int row = lin >> 5;
            int c4  = lin & 31;
            float4 v = *(const float4*)&Vg[(size_t)(j0 + row) * DK + c4 * 4];
            *(float4*)&KV[row * V_STRIDE + c4 * 4] = v;
        }
        __syncthreads();

        // Context accumulate: acc += P(64x64) @ V(64x128)
#pragma unroll 2
        for (int j = 0; j < 64; j++) {
            float4 v0 = *(const float4*)&KV[j * V_STRIDE + tx * 8];
            float4 v1 = *(const float4*)&KV[j * V_STRIDE + tx * 8 + 4];
            float p[4];
#pragma unroll
            for (int i = 0; i < 4; i++) p[i] = Ps[(ty * 4 + i) * QK_STRIDE + j];
#pragma unroll
            for (int i = 0; i < 4; i++) {
                acc[i][0] += p[i] * v0.x;  acc[i][1] += p[i] * v0.y;
                acc[i][2] += p[i] * v0.z;  acc[i][3] += p[i] * v0.w;
                acc[i][4] += p[i] * v1.x;  acc[i][5] += p[i] * v1.y;
                acc[i][6] += p[i] * v1.z;  acc[i][7] += p[i] * v1.w;
            }
        }
    }

    // Normalize and write context token-major: ctx[b*S+s][h*128+d]
    const int b = bh >> 4;
    const int h = bh & 15;
#pragma unroll
    for (int i = 0; i < 4; i++) {
        int m = ty * 4 + i;
        int s = q0 + m;
        float inv = 1.0f / row_l[m];
        float* o = &CTX[((size_t)(b * SEQ + s)) * DMODEL + h * DK + tx * 8];
#pragma unroll
        for (int d = 0; d < 8; d++) o[d] = acc[i][d] * inv;
    }
}

// ---------------------------------------------------------------------------
// Launch
// ---------------------------------------------------------------------------
extern "C" void kernel_launch(void* const* d_in, const int* in_sizes, int n_in,
                              void* d_out, int out_size)
{
    const float* x  = (const float*)d_in[0];
    const float* Wq = (const float*)d_in[1];
    const float* bq = (const float*)d_in[2];
    const float* Aq = (const float*)d_in[3];
    const float* Bq = (const float*)d_in[4];
    const float* Wk = (const float*)d_in[5];
    const float* bk = (const float*)d_in[6];
    const float* Ak = (const float*)d_in[7];
    const float* Bk = (const float*)d_in[8];
    const float* Wv = (const float*)d_in[9];
    const float* bv = (const float*)d_in[10];
    const float* Av = (const float*)d_in[11];
    const float* Bv = (const float*)d_in[12];
    const float* Wo = (const float*)d_in[13];
    const float* bo = (const float*)d_in[14];
    const float* Ao = (const float*)d_in[15];
    const float* Bo = (const float*)d_in[16];
    float* out = (float*)d_out;

    float *pt, *pto, *pq, *pk, *pv, *pctx;
    cudaGetSymbolAddress((void**)&pt,   g_t_qkv);
    cudaGetSymbolAddress((void**)&pto,  g_t_o);
    cudaGetSymbolAddress((void**)&pq,   g_q);
    cudaGetSymbolAddress((void**)&pk,   g_k);
    cudaGetSymbolAddress((void**)&pv,   g_v);
    cudaGetSymbolAddress((void**)&pctx, g_ctx);

    // 1) LoRA intermediates for q/k/v
    lora_t_kernel<3><<<MTOT, 256>>>(x, Aq, Ak, Av, pt, 24);

    // 2) Q/K/V projections (head-major output)
    dim3 gemm_grid(DMODEL / 128, MTOT / 128);   // (16, 32)
    gemm_lora_kernel<1><<<gemm_grid, 256>>>(x, Wq, bq, pt, Bq, pq, 24, 0);
    gemm_lora_kernel<1><<<gemm_grid, 256>>>(x, Wk, bk, pt, Bk, pk, 24, 8);
    gemm_lora_kernel<1><<<gemm_grid, 256>>>(x, Wv, bv, pt, Bv, pv, 24, 16);

    // 3) Fused attention
    cudaFuncSetAttribute(flash_kernel,
                         cudaFuncAttributeMaxDynamicSharedMemorySize,
                         FLASH_SMEM_BYTES);
    dim3 fgrid(SEQ / 64, BATCH * NHEADS);       // (32, 32)
    flash_kernel<<<fgrid, 256, FLASH_SMEM_BYTES>>>(pq, pk, pv, pctx);

    // 4) LoRA intermediate for output projection
    lora_t_kernel<1><<<MTOT, 256>>>(pctx, Ao, Ao, Ao, pto, 8);

    // 5) Output projection (row-major to d_out)
    gemm_lora_kernel<0><<<gemm_grid, 256>>>(pctx, Wo, bo, pto, Bo, out, 8, 0);
}

// round 3
// speedup vs baseline: 1.6697x; 1.6697x over previous
#include <cuda_runtime.h>
#include <cuda_bf16.h>
#include <math.h>
#include <cstdint>

// Problem constants
#define BATCH     2
#define SEQ       2048
#define DMODEL    2048
#define NHEADS    16
#define DK        128
#define MTOT      (BATCH * SEQ)          // 4096
#define LORA_SCALING 2.0f
#define SM_SCALE  0.08838834764831845f   // 1/sqrt(128)

// ---------------------------------------------------------------------------
// Scratch buffers
// ---------------------------------------------------------------------------
__device__ float g_t_qkv[MTOT * 24];
__device__ float g_t_o[MTOT * 8];
__device__ float g_q[BATCH * NHEADS * SEQ * DK];
__device__ float g_k[BATCH * NHEADS * SEQ * DK];
__device__ float g_v[BATCH * NHEADS * SEQ * DK];
__device__ float g_ctx[MTOT * DMODEL];
// bf16 split buffers
__device__ __nv_bfloat16 g_xhi[MTOT * DMODEL];
__device__ __nv_bfloat16 g_xlo[MTOT * DMODEL];
__device__ __nv_bfloat16 g_whi[4ull * DMODEL * DMODEL];
__device__ __nv_bfloat16 g_wlo[4ull * DMODEL * DMODEL];
__device__ __nv_bfloat16 g_chi[MTOT * DMODEL];
__device__ __nv_bfloat16 g_clo[MTOT * DMODEL];

// ---------------------------------------------------------------------------
// PTX helpers
// ---------------------------------------------------------------------------
__device__ __forceinline__ void cp16(uint32_t sm_dst, const void* g_src) {
    asm volatile("cp.async.cg.shared.global [%0], [%1], 16;" :: "r"(sm_dst), "l"(g_src) : "memory");
}
#define CP_COMMIT() asm volatile("cp.async.commit_group;" ::: "memory")
#define CP_WAIT(n)  asm volatile("cp.async.wait_group %0;" :: "n"(n) : "memory")

__device__ __forceinline__ uint32_t smem_u32(const void* p) {
    uint32_t a;
    asm("{ .reg .u64 t; cvta.to.shared.u64 t, %1; cvt.u32.u64 %0, t; }" : "=r"(a) : "l"(p));
    return a;
}
__device__ __forceinline__ uint32_t lds32(uint32_t addr) {
    uint32_t v;
    asm volatile("ld.shared.b32 %0, [%1];" : "=r"(v) : "r"(addr));
    return v;
}
#define MMA16816(d, a, b) \
    asm volatile("mma.sync.aligned.m16n8k16.row.col.f32.bf16.bf16.f32 " \
        "{%0,%1,%2,%3}, {%4,%5,%6,%7}, {%8,%9}, {%0,%1,%2,%3};" \
        : "+f"((d)[0]), "+f"((d)[1]), "+f"((d)[2]), "+f"((d)[3]) \
        : "r"((a)[0]), "r"((a)[1]), "r"((a)[2]), "r"((a)[3]), \
          "r"((b)[0]), "r"((b)[1]))

// ---------------------------------------------------------------------------
// Kernel: fp32 -> bf16 hi/lo split (vectorized)
// ---------------------------------------------------------------------------
__global__ void __launch_bounds__(256)
split_kernel(const float* __restrict__ src, __nv_bfloat16* __restrict__ hi,
             __nv_bfloat16* __restrict__ lo, int n4)
{
    int i = blockIdx.x * 256 + threadIdx.x;
    if (i >= n4) return;
    float4 v = ((const float4*)src)[i];
    __nv_bfloat16 h0 = __float2bfloat16_rn(v.x);
    __nv_bfloat16 h1 = __float2bfloat16_rn(v.y);
    __nv_bfloat16 h2 = __float2bfloat16_rn(v.z);
    __nv_bfloat16 h3 = __float2bfloat16_rn(v.w);
    __nv_bfloat16 l0 = __float2bfloat16_rn(v.x - __bfloat162float(h0));
    __nv_bfloat16 l1 = __float2bfloat16_rn(v.y - __bfloat162float(h1));
    __nv_bfloat16 l2 = __float2bfloat16_rn(v.z - __bfloat162float(h2));
    __nv_bfloat16 l3 = __float2bfloat16_rn(v.w - __bfloat162float(h3));
    __nv_bfloat162* hp = (__nv_bfloat162*)(hi + (size_t)i * 4);
    __nv_bfloat162* lp = (__nv_bfloat162*)(lo + (size_t)i * 4);
    hp[0] = __nv_bfloat162(h0, h1); hp[1] = __nv_bfloat162(h2, h3);
    lp[0] = __nv_bfloat162(l0, l1); lp[1] = __nv_bfloat162(l2, l3);
}

// ---------------------------------------------------------------------------
// Kernel: LoRA intermediate T[m][mat*8+r] = sum_k X[m][k] * A_mat[r][k]
// ---------------------------------------------------------------------------
template <int NMAT>
__global__ void __launch_bounds__(256)
lora_t_kernel(const float* __restrict__ X,
              const float* __restrict__ A0,
              const float* __restrict__ A1,
              const float* __restrict__ A2,
              float* __restrict__ T, int tstride)
{
    const int m = blockIdx.x;
    const int tid = threadIdx.x;
    const float* Amats[3] = {A0, A1, A2};

    float acc[NMAT * 8];
#pragma unroll
    for (int i = 0; i < NMAT * 8; i++) acc[i] = 0.0f;

    const float* xr = X + (size_t)m * DMODEL;
    for (int k = tid; k < DMODEL; k += 256) {
        float xv = xr[k];
#pragma unroll
        for (int mt = 0; mt < NMAT; mt++) {
            const float* Ap = Amats[mt];
#pragma unroll
            for (int r = 0; r < 8; r++)
                acc[mt * 8 + r] += xv * Ap[r * DMODEL + k];
        }
    }

    __shared__ float red[256];
#pragma unroll
    for (int o = 0; o < NMAT * 8; o++) {
        red[tid] = acc[o];
        __syncthreads();
        for (int s = 128; s > 0; s >>= 1) {
            if (tid < s) red[tid] += red[tid + s];
            __syncthreads();
        }
        if (tid == 0) T[(size_t)m * tstride + o] = red[0];
        __syncthreads();
    }
}

// ---------------------------------------------------------------------------
// mma.sync GEMM: Y[m][n] = sum_k X[m][k]*W[n][k] + bias[n] + 2*dot8(T[m],Bm[n])
// bf16 hi/lo split: acc = XhiWhi + XhiWlo + XloWhi (fp32 accumulate)
// Tile 128x128, 8 warps (2m x 4n, 64x32 each), K-block 64, 2-stage cp.async.
// Smem row stride 144B (72 bf16) -> conflict-free 32-bit fragment loads.
// MODE 0: row-major out.  MODE 1: head-major [b][h][s][d].
// ---------------------------------------------------------------------------
#define GKB        64                    // k per stage
#define ROWB       144                   // bytes per smem row (64 bf16 + pad)
#define MAT_BYTES  (128 * ROWB)          // 18432
#define STAGE_B    (4 * MAT_BYTES)       // 73728 (Ahi|Alo|Whi|Wlo)
#define GEMM_SMEM  (2 * STAGE_B)         // 147456
#define NKITER     (DMODEL / GKB)        // 32

__device__ __forceinline__ void gemm_load_stage(
    uint32_t sbase, int tid, int s,
    const __nv_bfloat16* gAh, const __nv_bfloat16* gAl,
    const __nv_bfloat16* gBh, const __nv_bfloat16* gBl)
{
    const uint32_t base = sbase + (s & 1) * STAGE_B;
    const int kt = s * GKB;
    const __nv_bfloat16* srcs[4] = {gAh, gAl, gBh, gBl};
#pragma unroll
    for (int mat = 0; mat < 4; mat++) {
        const __nv_bfloat16* g = srcs[mat];
        uint32_t mbase = base + mat * MAT_BYTES;
#pragma unroll
        for (int t = 0; t < 4; t++) {
            int chunk = tid + t * 256;        // 0..1023
            int row = chunk >> 3;             // 0..127
            int cc  = chunk & 7;              // 16B unit
            cp16(mbase + row * ROWB + cc * 16,
                 g + (size_t)row * DMODEL + kt + cc * 8);
        }
    }
    CP_COMMIT();
}

template <int MODE>
__global__ void __launch_bounds__(256)
gemm_mma_kernel(const __nv_bfloat16* __restrict__ Ahi, const __nv_bfloat16* __restrict__ Alo,
                const __nv_bfloat16* __restrict__ Bhi, const __nv_bfloat16* __restrict__ Blo,
                const float* __restrict__ bias, const float* __restrict__ T,
                const float* __restrict__ Bm, float* __restrict__ Yout,
                int tstride, int toff)
{
    extern __shared__ __align__(16) char smem[];
    uint32_t sbase = smem_u32(smem);
    const int tid  = threadIdx.x;
    const int wid  = tid >> 5;
    const int lane = tid & 31;
    const int g    = lane >> 2;
    const int t4   = lane & 3;
    const int wm   = (wid & 1) * 64;      // warp m offset
    const int wn   = (wid >> 1) * 32;     // warp n offset
    const int m0 = blockIdx.y * 128;
    const int n0 = blockIdx.x * 128;

    const __nv_bfloat16* gAh = Ahi + (size_t)m0 * DMODEL;
    const __nv_bfloat16* gAl = Alo + (size_t)m0 * DMODEL;
    const __nv_bfloat16* gBh = Bhi + (size_t)n0 * DMODEL;
    const __nv_bfloat16* gBl = Blo + (size_t)n0 * DMODEL;

    float acc[4][4][4];
#pragma unroll
    for (int i = 0; i < 4; i++)
#pragma unroll
        for (int j = 0; j < 4; j++)
#pragma unroll
            for (int r = 0; r < 4; r++) acc[i][j][r] = 0.0f;

    gemm_load_stage(sbase, tid, 0, gAh, gAl, gBh, gBl);
    gemm_load_stage(sbase, tid, 1, gAh, gAl, gBh, gBl);

    for (int s = 0; s < NKITER; s++) {
        if (s == NKITER - 1) { CP_WAIT(0); } else { CP_WAIT(1); }
        __syncthreads();

        const uint32_t st = sbase + (s & 1) * STAGE_B;
        // per-warp/lane fragment base addresses (bytes)
        const uint32_t aHiB = st + 0 * MAT_BYTES + (wm + g) * ROWB + t4 * 4;
        const uint32_t aLoB = st + 1 * MAT_BYTES + (wm + g) * ROWB + t4 * 4;
        const uint32_t bHiB = st + 2 * MAT_BYTES + (wn + g) * ROWB + t4 * 4;
        const uint32_t bLoB = st + 3 * MAT_BYTES + (wn + g) * ROWB + t4 * 4;

#pragma unroll
        for (int kh = 0; kh < 4; kh++) {          // four k16 halves (byte off 32 each)
            const uint32_t ko = kh * 32;
            uint32_t ah[4][4], al[4][4], bh[4][2], bl[4][2];
#pragma unroll
            for (int mi = 0; mi < 4; mi++) {
                uint32_t r = aHiB + mi * (16 * ROWB) + ko;
                ah[mi][0] = lds32(r);
                ah[mi][1] = lds32(r + 8 * ROWB);
                ah[mi][2] = lds32(r + 16);
                ah[mi][3] = lds32(r + 8 * ROWB + 16);
            }
#pragma unroll
            for (int ni = 0; ni < 4; ni++) {
                uint32_t r = bHiB + ni * (8 * ROWB) + ko;
                bh[ni][0] = lds32(r);
                bh[ni][1] = lds32(r + 16);
            }
#pragma unroll
            for (int mi = 0; mi < 4; mi++)
#pragma unroll
                for (int ni = 0; ni < 4; ni++)
                    MMA16816(acc[mi][ni], ah[mi], bh[ni]);

#pragma unroll
            for (int ni = 0; ni < 4; ni++) {
                uint32_t r = bLoB + ni * (8 * ROWB) + ko;
                bl[ni][0] = lds32(r);
                bl[ni][1] = lds32(r + 16);
            }
#pragma unroll
            for (int mi = 0; mi < 4; mi++)
#pragma unroll
                for (int ni = 0; ni < 4; ni++)
                    MMA16816(acc[mi][ni], ah[mi], bl[ni]);

#pragma unroll
            for (int mi = 0; mi < 4; mi++) {
                uint32_t r = aLoB + mi * (16 * ROWB) + ko;
                al[mi][0] = lds32(r);
                al[mi][1] = lds32(r + 8 * ROWB);
                al[mi][2] = lds32(r + 16);
                al[mi][3] = lds32(r + 8 * ROWB + 16);
            }
#pragma unroll
            for (int mi = 0; mi < 4; mi++)
#pragma unroll
                for (int ni = 0; ni < 4; ni++)
                    MMA16816(acc[mi][ni], al[mi], bh[ni]);
        }

        __syncthreads();
        if (s + 2 < NKITER)
            gemm_load_stage(sbase, tid, s + 2, gAh, gAl, gBh, gBl);
    }

    // ---- Epilogue: stage T (128x8) and Bm (128x8) in smem, add bias + lora ----
    __syncthreads();
    float* sT = (float*)smem;           // 4096 B
    float* sB = (float*)(smem + 4096);  // 4096 B
    {
        int row = tid >> 1;
        int half = tid & 1;
        float4 tv = *(const float4*)&T[(size_t)(m0 + row) * tstride + toff + half * 4];
        *(float4*)&sT[row * 8 + half * 4] = tv;
        float4 bv = *(const float4*)&Bm[(size_t)(n0 + row) * 8 + half * 4];
        *(float4*)&sB[row * 8 + half * 4] = bv;
    }
    __syncthreads();

#pragma unroll
    for (int mi = 0; mi < 4; mi++) {
        int rl0 = wm + mi * 16 + g;       // local rows rl0, rl0+8
#pragma unroll
        for (int rr = 0; rr < 2; rr++) {
            int rl = rl0 + rr * 8;
            int m = m0 + rl;
            const float* tr = &sT[rl * 8];
#pragma unroll
            for (int ni = 0; ni < 4; ni++) {
                int cl = wn + ni * 8 + t4 * 2;
                int n = n0 + cl;
                float d0 = acc[mi][ni][rr * 2 + 0];
                float d1 = acc[mi][ni][rr * 2 + 1];
                const float* b0 = &sB[cl * 8];
                const float* b1 = &sB[(cl + 1) * 8];
                float dot0 = 0.0f, dot1 = 0.0f;
#pragma unroll
                for (int r = 0; r < 8; r++) { dot0 += tr[r] * b0[r]; dot1 += tr[r] * b1[r]; }
                float2 y;
                y.x = d0 + bias[n]     + LORA_SCALING * dot0;
                y.y = d1 + bias[n + 1] + LORA_SCALING * dot1;
                if (MODE == 0) {
                    *(float2*)&Yout[(size_t)m * DMODEL + n] = y;
                } else {
                    int bb = m >> 11, ss = m & 2047;
                    int h = n >> 7, d = n & 127;
                    *(float2*)&Yout[((((size_t)bb * NHEADS + h) * SEQ + ss) << 7) + d] = y;
                }
            }
        }
    }
}

// ---------------------------------------------------------------------------
// Fused flash attention (fp32, unchanged)
// ---------------------------------------------------------------------------
#define QK_STRIDE 68
#define V_STRIDE  132
#define FLASH_SMEM_FLOATS (128*QK_STRIDE + 128*QK_STRIDE + 64*QK_STRIDE + 192)
#define FLASH_SMEM_BYTES  (FLASH_SMEM_FLOATS * 4)

__global__ void __launch_bounds__(256)
flash_kernel(const float* __restrict__ Q,
             const float* __restrict__ K,
             const float* __restrict__ V,
             float* __restrict__ CTX)
{
    extern __shared__ float sm[];
    float* Qst    = sm;
    float* KV     = sm + 128 * QK_STRIDE;
    float* Ps     = KV + 128 * QK_STRIDE;
    float* row_m  = Ps + 64 * QK_STRIDE;
    float* row_l  = row_m + 64;
    float* row_sc = row_l + 64;

    const int tid = threadIdx.x;
    const int ty = tid >> 4;
    const int tx = tid & 15;
    const int bh = blockIdx.y;
    const int q0 = blockIdx.x * 64;

    const float* Qg = Q + ((size_t)bh * SEQ + q0) * DK;
    const float* Kg = K + (size_t)bh * SEQ * DK;
    const float* Vg = V + (size_t)bh * SEQ * DK;

#pragma unroll
    for (int w = 0; w < 8; w++) {
        int lin = tid + w * 256;
        int row = lin >> 5;
        int c4  = lin & 31;
        float4 v = *(const float4*)&Qg[(size_t)row * DK + c4 * 4];
        Qst[(c4 * 4 + 0) * QK_STRIDE + row] = v.x;
        Qst[(c4 * 4 + 1) * QK_STRIDE + row] = v.y;
        Qst[(c4 * 4 + 2) * QK_STRIDE + row] = v.z;
        Qst[(c4 * 4 + 3) * QK_STRIDE + row] = v.w;
    }
    if (tid < 64) { row_m[tid] = -INFINITY; row_l[tid] = 0.0f; }

    float acc[4][8];
#pragma unroll
    for (int i = 0; i < 4; i++)
#pragma unroll
        for (int d = 0; d < 8; d++) acc[i][d] = 0.0f;

    for (int j0 = 0; j0 < SEQ; j0 += 64) {
        __syncthreads();
#pragma unroll
        for (int w = 0; w < 8; w++) {
            int lin = tid + w * 256;
            int row = lin >> 5;
            int c4  = lin & 31;
            float4 v = *(const float4*)&Kg[(size_t)(j0 + row) * DK + c4 * 4];
            KV[(c4 * 4 + 0) * QK_STRIDE + row] = v.x;
            KV[(c4 * 4 + 1) * QK_STRIDE + row] = v.y;
            KV[(c4 * 4 + 2) * QK_STRIDE + row] = v.z;
            KV[(c4 * 4 + 3) * QK_STRIDE + row] = v.w;
        }
        __syncthreads();

        float sc[4][4];
#pragma unroll
        for (int i = 0; i < 4; i++)
#pragma unroll
            for (int j = 0; j < 4; j++) sc[i][j] = 0.0f;

#pragma unroll 4
        for (int k = 0; k < DK; k++) {
            float4 qv = *(const float4*)&Qst[k * QK_STRIDE + ty * 4];
            float4 kv = *(const float4*)&KV[k * QK_STRIDE + tx * 4];
            float rq[4] = {qv.x, qv.y, qv.z, qv.w};
            float rk[4] = {kv.x, kv.y, kv.z, kv.w};
#pragma unroll
            for (int i = 0; i < 4; i++)
#pragma unroll
                for (int j = 0; j < 4; j++)
                    sc[i][j] += rq[i] * rk[j];
        }
#pragma unroll
        for (int i = 0; i < 4; i++) {
            float4 ov = make_float4(sc[i][0] * SM_SCALE, sc[i][1] * SM_SCALE,
                                    sc[i][2] * SM_SCALE, sc[i][3] * SM_SCALE);
            *(float4*)&Ps[(ty * 4 + i) * QK_STRIDE + tx * 4] = ov;
        }
        __syncthreads();

        {
            int row = tid >> 2;
            int q   = tid & 3;
            float* pr = &Ps[row * QK_STRIDE + q * 16];
            float mx = -INFINITY;
#pragma unroll
            for (int c = 0; c < 16; c++) mx = fmaxf(mx, pr[c]);
            mx = fmaxf(mx, __shfl_xor_sync(0xffffffffu, mx, 1));
            mx = fmaxf(mx, __shfl_xor_sync(0xffffffffu, mx, 2));
            float mold = row_m[row];
            float mnew = fmaxf(mold, mx);
            float scl  = __expf(mold - mnew);
            float ls = 0.0f;
#pragma unroll
            for (int c = 0; c < 16; c++) {
                float e = __expf(pr[c] - mnew);
                pr[c] = e;
                ls += e;
            }
            ls += __shfl_xor_sync(0xffffffffu, ls, 1);
            ls += __shfl_xor_sync(0xffffffffu, ls, 2);
            if (q == 0) {
                row_l[row] = row_l[row] * scl + ls;
                row_m[row] = mnew;
                row_sc[row] = scl;
            }
        }
        __syncthreads();

#pragma unroll
        for (int i = 0; i < 4; i++) {
            float f = row_sc[ty * 4 + i];
#pragma unroll
            for (int d = 0; d < 8; d++) acc[i][d] *= f;
        }

#pragma unroll
        for (int w = 0; w < 8; w++) {
            int lin = tid + w * 256;
            int row = lin >> 5;
            int c4  = lin & 31;
            float4 v = *(const float4*)&Vg[(size_t)(j0 + row) * DK + c4 * 4];
            *(float4*)&KV[row * V_STRIDE + c4 * 4] = v;
        }
        __syncthreads();

#pragma unroll 2
        for (int j = 0; j < 64; j++) {
            float4 v0 = *(const float4*)&KV[j * V_STRIDE + tx * 8];
            float4 v1 = *(const float4*)&KV[j * V_STRIDE + tx * 8 + 4];
            float p[4];
#pragma unroll
            for (int i = 0; i < 4; i++) p[i] = Ps[(ty * 4 + i) * QK_STRIDE + j];
#pragma unroll
            for (int i = 0; i < 4; i++) {
                acc[i][0] += p[i] * v0.x;  acc[i][1] += p[i] * v0.y;
                acc[i][2] += p[i] * v0.z;  acc[i][3] += p[i] * v0.w;
                acc[i][4] += p[i] * v1.x;  acc[i][5] += p[i] * v1.y;
                acc[i][6] += p[i] * v1.z;  acc[i][7] += p[i] * v1.w;
            }
        }
    }

    const int b = bh >> 4;
    const int h = bh & 15;
#pragma unroll
    for (int i = 0; i < 4; i++) {
        int mm = ty * 4 + i;
        int s = q0 + mm;
        float inv = 1.0f / row_l[mm];
        float* o = &CTX[((size_t)(b * SEQ + s)) * DMODEL + h * DK + tx * 8];
#pragma unroll
        for (int d = 0; d < 8; d++) o[d] = acc[i][d] * inv;
    }
}

// ---------------------------------------------------------------------------
// Launch
// ---------------------------------------------------------------------------
extern "C" void kernel_launch(void* const* d_in, const int* in_sizes, int n_in,
                              void* d_out, int out_size)
{
    const float* x  = (const float*)d_in[0];
    const float* Wq = (const float*)d_in[1];
    const float* bq = (const float*)d_in[2];
    const float* Aq = (const float*)d_in[3];
    const float* Bq = (const float*)d_in[4];
    const float* Wk = (const float*)d_in[5];
    const float* bk = (const float*)d_in[6];
    const float* Ak = (const float*)d_in[7];
    const float* Bk = (const float*)d_in[8];
    const float* Wv = (const float*)d_in[9];
    const float* bv = (const float*)d_in[10];
    const float* Av = (const float*)d_in[11];
    const float* Bv = (const float*)d_in[12];
    const float* Wo = (const float*)d_in[13];
    const float* bo = (const float*)d_in[14];
    const float* Ao = (const float*)d_in[15];
    const float* Bo = (const float*)d_in[16];
    float* out = (float*)d_out;

    float *pt, *pto, *pq, *pk, *pv, *pctx;
    __nv_bfloat16 *pxhi, *pxlo, *pwhi, *pwlo, *pchi, *pclo;
    cudaGetSymbolAddress((void**)&pt,   g_t_qkv);
    cudaGetSymbolAddress((void**)&pto,  g_t_o);
    cudaGetSymbolAddress((void**)&pq,   g_q);
    cudaGetSymbolAddress((void**)&pk,   g_k);
    cudaGetSymbolAddress((void**)&pv,   g_v);
    cudaGetSymbolAddress((void**)&pctx, g_ctx);
    cudaGetSymbolAddress((void**)&pxhi, g_xhi);
    cudaGetSymbolAddress((void**)&pxlo, g_xlo);
    cudaGetSymbolAddress((void**)&pwhi, g_whi);
    cudaGetSymbolAddress((void**)&pwlo, g_wlo);
    cudaGetSymbolAddress((void**)&pchi, g_chi);
    cudaGetSymbolAddress((void**)&pclo, g_clo);

    cudaFuncSetAttribute(gemm_mma_kernel<0>,
                         cudaFuncAttributeMaxDynamicSharedMemorySize, GEMM_SMEM);
    cudaFuncSetAttribute(gemm_mma_kernel<1>,
                         cudaFuncAttributeMaxDynamicSharedMemorySize, GEMM_SMEM);
    cudaFuncSetAttribute(flash_kernel,
                         cudaFuncAttributeMaxDynamicSharedMemorySize, FLASH_SMEM_BYTES);

    const size_t WSZ = (size_t)DMODEL * DMODEL;
    const int nX4 = MTOT * DMODEL / 4;
    const int nW4 = (int)(WSZ / 4);
    const int sg  = 256;

    // 1) Splits: x and the 4 weight matrices
    split_kernel<<<(nX4 + sg - 1) / sg, sg>>>(x, pxhi, pxlo, nX4);
    split_kernel<<<(nW4 + sg - 1) / sg, sg>>>(Wq, pwhi + 0 * WSZ, pwlo + 0 * WSZ, nW4);
    split_kernel<<<(nW4 + sg - 1) / sg, sg>>>(Wk, pwhi + 1 * WSZ, pwlo + 1 * WSZ, nW4);
    split_kernel<<<(nW4 + sg - 1) / sg, sg>>>(Wv, pwhi + 2 * WSZ, pwlo + 2 * WSZ, nW4);
    split_kernel<<<(nW4 + sg - 1) / sg, sg>>>(Wo, pwhi + 3 * WSZ, pwlo + 3 * WSZ, nW4);

    // 2) LoRA intermediates for q/k/v
    lora_t_kernel<3><<<MTOT, 256>>>(x, Aq, Ak, Av, pt, 24);

    // 3) Q/K/V projections (mma.sync, head-major output)
    dim3 ggrid(DMODEL / 128, MTOT / 128);    // (16, 32)
    gemm_mma_kernel<1><<<ggrid, 256, GEMM_SMEM>>>(pxhi, pxlo, pwhi + 0 * WSZ, pwlo + 0 * WSZ,
                                                  bq, pt, Bq, pq, 24, 0);
    gemm_mma_kernel<1><<<ggrid, 256, GEMM_SMEM>>>(pxhi, pxlo, pwhi + 1 * WSZ, pwlo + 1 * WSZ,
                                                  bk, pt, Bk, pk, 24, 8);
    gemm_mma_kernel<1><<<ggrid, 256, GEMM_SMEM>>>(pxhi, pxlo, pwhi + 2 * WSZ, pwlo + 2 * WSZ,
                                                  bv, pt, Bv, pv, 24, 16);

    // 4) Fused attention
    dim3 fgrid(SEQ / 64, BATCH * NHEADS);
    flash_kernel<<<fgrid, 256, FLASH_SMEM_BYTES>>>(pq, pk, pv, pctx);

    // 5) Output-projection path: split ctx, LoRA T, GEMM
    split_kernel<<<(nX4 + sg - 1) / sg, sg>>>(pctx, pchi, pclo, nX4);
    lora_t_kernel<1><<<MTOT, 256>>>(pctx, Ao, Ao, Ao, pto, 8);
    gemm_mma_kernel<0><<<ggrid, 256, GEMM_SMEM>>>(pchi, pclo, pwhi + 3 * WSZ, pwlo + 3 * WSZ,
                                                  bo, pto, Bo, out, 8, 0);
}

// round 4
// speedup vs baseline: 2.8773x; 1.7233x over previous
#include <cuda_runtime.h>
#include <cuda_bf16.h>
#include <math.h>
#include <cstdint>

// Problem constants
#define BATCH     2
#define SEQ       2048
#define DMODEL    2048
#define NHEADS    16
#define DK        128
#define MTOT      (BATCH * SEQ)          // 4096
#define LORA_SCALING 2.0f
#define SM_SCALE  0.08838834764831845f   // 1/sqrt(128)
#define NBH       (BATCH * NHEADS)       // 32

// ---------------------------------------------------------------------------
// Scratch buffers
// ---------------------------------------------------------------------------
#define HSZ (BATCH * NHEADS * SEQ * DK)  // 8388608
__device__ float g_t_qkv[MTOT * 24];
__device__ float g_t_o[MTOT * 8];
__device__ float g_ctx[MTOT * DMODEL];
__device__ __nv_bfloat16 g_xhi[MTOT * DMODEL];
__device__ __nv_bfloat16 g_xlo[MTOT * DMODEL];
__device__ __nv_bfloat16 g_whi[4ull * DMODEL * DMODEL];
__device__ __nv_bfloat16 g_wlo[4ull * DMODEL * DMODEL];
__device__ __nv_bfloat16 g_chi[MTOT * DMODEL];
__device__ __nv_bfloat16 g_clo[MTOT * DMODEL];
// head-major [b][h][s][d] hi/lo
__device__ __nv_bfloat16 g_qhi[HSZ], g_qlo[HSZ];
__device__ __nv_bfloat16 g_khi[HSZ], g_klo[HSZ];
__device__ __nv_bfloat16 g_vhi[HSZ], g_vlo[HSZ];
// transposed V [b][h][d][s] hi/lo
__device__ __nv_bfloat16 g_vthi[HSZ], g_vtlo[HSZ];

// ---------------------------------------------------------------------------
// PTX helpers
// ---------------------------------------------------------------------------
__device__ __forceinline__ void cp16(uint32_t sm_dst, const void* g_src) {
    asm volatile("cp.async.cg.shared.global [%0], [%1], 16;" :: "r"(sm_dst), "l"(g_src) : "memory");
}
#define CP_COMMIT() asm volatile("cp.async.commit_group;" ::: "memory")
#define CP_WAIT(n)  asm volatile("cp.async.wait_group %0;" :: "n"(n) : "memory")

__device__ __forceinline__ uint32_t smem_u32(const void* p) {
    uint32_t a;
    asm("{ .reg .u64 t; cvta.to.shared.u64 t, %1; cvt.u32.u64 %0, t; }" : "=r"(a) : "l"(p));
    return a;
}
__device__ __forceinline__ uint32_t lds32(uint32_t addr) {
    uint32_t v;
    asm volatile("ld.shared.b32 %0, [%1];" : "=r"(v) : "r"(addr));
    return v;
}
#define MMA16816(d, a, b) \
    asm volatile("mma.sync.aligned.m16n8k16.row.col.f32.bf16.bf16.f32 " \
        "{%0,%1,%2,%3}, {%4,%5,%6,%7}, {%8,%9}, {%0,%1,%2,%3};" \
        : "+f"((d)[0]), "+f"((d)[1]), "+f"((d)[2]), "+f"((d)[3]) \
        : "r"((a)[0]), "r"((a)[1]), "r"((a)[2]), "r"((a)[3]), \
          "r"((b)[0]), "r"((b)[1]))

// split two floats into packed bf16 hi / lo pairs (low half = first arg)
__device__ __forceinline__ void split2(float a, float b, uint32_t& hi, uint32_t& lo) {
    __nv_bfloat16 ha = __float2bfloat16_rn(a), hb = __float2bfloat16_rn(b);
    __nv_bfloat16 la = __float2bfloat16_rn(a - __bfloat162float(ha));
    __nv_bfloat16 lb = __float2bfloat16_rn(b - __bfloat162float(hb));
    __nv_bfloat162 H(ha, hb), L(la, lb);
    hi = *(uint32_t*)&H;
    lo = *(uint32_t*)&L;
}

// ---------------------------------------------------------------------------
// fp32 -> bf16 hi/lo split
// ---------------------------------------------------------------------------
__global__ void __launch_bounds__(256)
split_kernel(const float* __restrict__ src, __nv_bfloat16* __restrict__ hi,
             __nv_bfloat16* __restrict__ lo, int n4)
{
    int i = blockIdx.x * 256 + threadIdx.x;
    if (i >= n4) return;
    float4 v = ((const float4*)src)[i];
    __nv_bfloat16 h0 = __float2bfloat16_rn(v.x);
    __nv_bfloat16 h1 = __float2bfloat16_rn(v.y);
    __nv_bfloat16 h2 = __float2bfloat16_rn(v.z);
    __nv_bfloat16 h3 = __float2bfloat16_rn(v.w);
    __nv_bfloat16 l0 = __float2bfloat16_rn(v.x - __bfloat162float(h0));
    __nv_bfloat16 l1 = __float2bfloat16_rn(v.y - __bfloat162float(h1));
    __nv_bfloat16 l2 = __float2bfloat16_rn(v.z - __bfloat162float(h2));
    __nv_bfloat16 l3 = __float2bfloat16_rn(v.w - __bfloat162float(h3));
    __nv_bfloat162* hp = (__nv_bfloat162*)(hi + (size_t)i * 4);
    __nv_bfloat162* lp = (__nv_bfloat162*)(lo + (size_t)i * 4);
    hp[0] = __nv_bfloat162(h0, h1); hp[1] = __nv_bfloat162(h2, h3);
    lp[0] = __nv_bfloat162(l0, l1); lp[1] = __nv_bfloat162(l2, l3);
}

// ---------------------------------------------------------------------------
// LoRA intermediate T[m][mat*8+r] = sum_k X[m][k] * A_mat[r][k]
// ---------------------------------------------------------------------------
template <int NMAT>
__global__ void __launch_bounds__(256)
lora_t_kernel(const float* __restrict__ X,
              const float* __restrict__ A0,
              const float* __restrict__ A1,
              const float* __restrict__ A2,
              float* __restrict__ T, int tstride)
{
    const int m = blockIdx.x;
    const int tid = threadIdx.x;
    const float* Amats[3] = {A0, A1, A2};

    float acc[NMAT * 8];
#pragma unroll
    for (int i = 0; i < NMAT * 8; i++) acc[i] = 0.0f;

    const float* xr = X + (size_t)m * DMODEL;
    for (int k = tid; k < DMODEL; k += 256) {
        float xv = xr[k];
#pragma unroll
        for (int mt = 0; mt < NMAT; mt++) {
            const float* Ap = Amats[mt];
#pragma unroll
            for (int r = 0; r < 8; r++)
                acc[mt * 8 + r] += xv * Ap[r * DMODEL + k];
        }
    }

    __shared__ float red[256];
#pragma unroll
    for (int o = 0; o < NMAT * 8; o++) {
        red[tid] = acc[o];
        __syncthreads();
        for (int s = 128; s > 0; s >>= 1) {
            if (tid < s) red[tid] += red[tid + s];
            __syncthreads();
        }
        if (tid == 0) T[(size_t)m * tstride + o] = red[0];
        __syncthreads();
    }
}

// ---------------------------------------------------------------------------
// mma.sync GEMM (as R3). MODE 0: fp32 row-major. MODE 1: bf16 hi/lo head-major.
// ---------------------------------------------------------------------------
#define GKB        64
#define ROWB       144
#define MAT_BYTES  (128 * ROWB)
#define STAGE_B    (4 * MAT_BYTES)
#define GEMM_SMEM  (2 * STAGE_B)
#define NKITER     (DMODEL / GKB)

__device__ __forceinline__ void gemm_load_stage(
    uint32_t sbase, int tid, int s,
    const __nv_bfloat16* gAh, const __nv_bfloat16* gAl,
    const __nv_bfloat16* gBh, const __nv_bfloat16* gBl)
{
    const uint32_t base = sbase + (s & 1) * STAGE_B;
    const int kt = s * GKB;
    const __nv_bfloat16* srcs[4] = {gAh, gAl, gBh, gBl};
#pragma unroll
    for (int mat = 0; mat < 4; mat++) {
        const __nv_bfloat16* g = srcs[mat];
        uint32_t mbase = base + mat * MAT_BYTES;
#pragma unroll
        for (int t = 0; t < 4; t++) {
            int chunk = tid + t * 256;
            int row = chunk >> 3;
            int cc  = chunk & 7;
            cp16(mbase + row * ROWB + cc * 16,
                 g + (size_t)row * DMODEL + kt + cc * 8);
        }
    }
    CP_COMMIT();
}

template <int MODE>
__global__ void __launch_bounds__(256)
gemm_mma_kernel(const __nv_bfloat16* __restrict__ Ahi, const __nv_bfloat16* __restrict__ Alo,
                const __nv_bfloat16* __restrict__ Bhi, const __nv_bfloat16* __restrict__ Blo,
                const float* __restrict__ bias, const float* __restrict__ T,
                const float* __restrict__ Bm,
                float* __restrict__ YoutF,
                __nv_bfloat16* __restrict__ YoutH, __nv_bfloat16* __restrict__ YoutL,
                int tstride, int toff)
{
    extern __shared__ __align__(16) char smem[];
    uint32_t sbase = smem_u32(smem);
    const int tid  = threadIdx.x;
    const int wid  = tid >> 5;
    const int lane = tid & 31;
    const int g    = lane >> 2;
    const int t4   = lane & 3;
    const int wm   = (wid & 1) * 64;
    const int wn   = (wid >> 1) * 32;
    const int m0 = blockIdx.y * 128;
    const int n0 = blockIdx.x * 128;

    const __nv_bfloat16* gAh = Ahi + (size_t)m0 * DMODEL;
    const __nv_bfloat16* gAl = Alo + (size_t)m0 * DMODEL;
    const __nv_bfloat16* gBh = Bhi + (size_t)n0 * DMODEL;
    const __nv_bfloat16* gBl = Blo + (size_t)n0 * DMODEL;

    float acc[4][4][4];
#pragma unroll
    for (int i = 0; i < 4; i++)
#pragma unroll
        for (int j = 0; j < 4; j++)
#pragma unroll
            for (int r = 0; r < 4; r++) acc[i][j][r] = 0.0f;

    gemm_load_stage(sbase, tid, 0, gAh, gAl, gBh, gBl);
    gemm_load_stage(sbase, tid, 1, gAh, gAl, gBh, gBl);

    for (int s = 0; s < NKITER; s++) {
        if (s == NKITER - 1) { CP_WAIT(0); } else { CP_WAIT(1); }
        __syncthreads();

        const uint32_t st = sbase + (s & 1) * STAGE_B;
        const uint32_t aHiB = st + 0 * MAT_BYTES + (wm + g) * ROWB + t4 * 4;
        const uint32_t aLoB = st + 1 * MAT_BYTES + (wm + g) * ROWB + t4 * 4;
        const uint32_t bHiB = st + 2 * MAT_BYTES + (wn + g) * ROWB + t4 * 4;
        const uint32_t bLoB = st + 3 * MAT_BYTES + (wn + g) * ROWB + t4 * 4;

#pragma unroll
        for (int kh = 0; kh < 4; kh++) {
            const uint32_t ko = kh * 32;
            uint32_t ah[4][4], al[4][4], bh[4][2], bl[4][2];
#pragma unroll
            for (int mi = 0; mi < 4; mi++) {
                uint32_t r = aHiB + mi * (16 * ROWB) + ko;
                ah[mi][0] = lds32(r);
                ah[mi][1] = lds32(r + 8 * ROWB);
                ah[mi][2] = lds32(r + 16);
                ah[mi][3] = lds32(r + 8 * ROWB + 16);
            }
#pragma unroll
            for (int ni = 0; ni < 4; ni++) {
                uint32_t r = bHiB + ni * (8 * ROWB) + ko;
                bh[ni][0] = lds32(r);
                bh[ni][1] = lds32(r + 16);
            }
#pragma unroll
            for (int mi = 0; mi < 4; mi++)
#pragma unroll
                for (int ni = 0; ni < 4; ni++)
                    MMA16816(acc[mi][ni], ah[mi], bh[ni]);

#pragma unroll
            for (int ni = 0; ni < 4; ni++) {
                uint32_t r = bLoB + ni * (8 * ROWB) + ko;
                bl[ni][0] = lds32(r);
                bl[ni][1] = lds32(r + 16);
            }
#pragma unroll
            for (int mi = 0; mi < 4; mi++)
#pragma unroll
                for (int ni = 0; ni < 4; ni++)
                    MMA16816(acc[mi][ni], ah[mi], bl[ni]);

#pragma unroll
            for (int mi = 0; mi < 4; mi++) {
                uint32_t r = aLoB + mi * (16 * ROWB) + ko;
                al[mi][0] = lds32(r);
                al[mi][1] = lds32(r + 8 * ROWB);
                al[mi][2] = lds32(r + 16);
                al[mi][3] = lds32(r + 8 * ROWB + 16);
            }
#pragma unroll
            for (int mi = 0; mi < 4; mi++)
#pragma unroll
                for (int ni = 0; ni < 4; ni++)
                    MMA16816(acc[mi][ni], al[mi], bh[ni]);
        }

        __syncthreads();
        if (s + 2 < NKITER)
            gemm_load_stage(sbase, tid, s + 2, gAh, gAl, gBh, gBl);
    }

    // Epilogue
    __syncthreads();
    float* sT = (float*)smem;
    float* sB = (float*)(smem + 4096);
    {
        int row = tid >> 1;
        int half = tid & 1;
        float4 tv = *(const float4*)&T[(size_t)(m0 + row) * tstride + toff + half * 4];
        *(float4*)&sT[row * 8 + half * 4] = tv;
        float4 bv = *(const float4*)&Bm[(size_t)(n0 + row) * 8 + half * 4];
        *(float4*)&sB[row * 8 + half * 4] = bv;
    }
    __syncthreads();

#pragma unroll
    for (int mi = 0; mi < 4; mi++) {
        int rl0 = wm + mi * 16 + g;
#pragma unroll
        for (int rr = 0; rr < 2; rr++) {
            int rl = rl0 + rr * 8;
            int m = m0 + rl;
            const float* tr = &sT[rl * 8];
#pragma unroll
            for (int ni = 0; ni < 4; ni++) {
                int cl = wn + ni * 8 + t4 * 2;
                int n = n0 + cl;
                float d0 = acc[mi][ni][rr * 2 + 0];
                float d1 = acc[mi][ni][rr * 2 + 1];
                const float* b0 = &sB[cl * 8];
                const float* b1 = &sB[(cl + 1) * 8];
                float dot0 = 0.0f, dot1 = 0.0f;
#pragma unroll
                for (int r = 0; r < 8; r++) { dot0 += tr[r] * b0[r]; dot1 += tr[r] * b1[r]; }
                float yx = d0 + bias[n]     + LORA_SCALING * dot0;
                float yy = d1 + bias[n + 1] + LORA_SCALING * dot1;
                if (MODE == 0) {
                    *(float2*)&YoutF[(size_t)m * DMODEL + n] = make_float2(yx, yy);
                } else {
                    int bb = m >> 11, ss = m & 2047;
                    int h = n >> 7, d = n & 127;
                    size_t idx = ((((size_t)bb * NHEADS + h) * SEQ + ss) << 7) + d;
                    uint32_t hv, lv;
                    split2(yx, yy, hv, lv);
                    *(uint32_t*)&YoutH[idx] = hv;
                    *(uint32_t*)&YoutL[idx] = lv;
                }
            }
        }
    }
}

// ---------------------------------------------------------------------------
// V transpose: [bh][s][d] -> [bh][d][s], hi and lo in one kernel.
// 64x64 tiles.
// ---------------------------------------------------------------------------
__global__ void __launch_bounds__(256)
vtrans_kernel(const __nv_bfloat16* __restrict__ vh, const __nv_bfloat16* __restrict__ vl,
              __nv_bfloat16* __restrict__ vth, __nv_bfloat16* __restrict__ vtl)
{
    __shared__ __nv_bfloat16 tile[64][65];
    const int tid = threadIdx.x;
    const int bh = blockIdx.z;
    const int s0 = blockIdx.x * 64;
    const int d0 = blockIdx.y * 64;

    const __nv_bfloat16* srcs[2] = {vh, vl};
    __nv_bfloat16* dsts[2] = {vth, vtl};

#pragma unroll
    for (int pass = 0; pass < 2; pass++) {
        const __nv_bfloat16* src = srcs[pass] + ((size_t)bh * SEQ + s0) * DK + d0;
        __nv_bfloat16* dst = dsts[pass] + ((size_t)bh * DK + d0) * SEQ + s0;
        // load 64x64
        {
            int i = tid >> 2;          // 0..63
            int jp = tid & 3;          // 4 groups of 8 pairs
#pragma unroll
            for (int c = 0; c < 8; c++) {
                int j2 = jp * 8 + c;   // pair index 0..31
                __nv_bfloat162 v = *(const __nv_bfloat162*)(src + (size_t)i * DK + j2 * 2);
                tile[i][j2 * 2] = v.x;
                tile[i][j2 * 2 + 1] = v.y;
            }
        }
        __syncthreads();
        // write transposed
        {
            int r = tid >> 5;          // 0..7
            int wp = tid & 31;
#pragma unroll
            for (int p = 0; p < 8; p++) {
                int row = r + p * 8;   // d index 0..63
                __nv_bfloat162 v(tile[2 * wp][row], tile[2 * wp + 1][row]);
                *(__nv_bfloat162*)(dst + (size_t)row * SEQ + 2 * wp) = v;
            }
        }
        __syncthreads();
    }
}

// ---------------------------------------------------------------------------
// Flash attention on mma.sync bf16 hi/lo.
// Block = 128 queries of one (b,h), 256 threads (8 warps x 16 rows).
// KV tiles of 64, double-buffered cp.async.
// ---------------------------------------------------------------------------
#define FQROW  272                      // Q/K smem row bytes (128 bf16 + 16 pad)
#define FQSZ   (128 * FQROW)            // 34816
#define FQSZ2  (2 * FQSZ)               // 69632
#define FKSZ   (64 * FQROW)             // 17408
#define FVROW  144                      // VT row bytes (64 bf16 + 16 pad)
#define FVSZ   (128 * FVROW)            // 18432
#define FSTAGE (2 * FKSZ + 2 * FVSZ)    // 71680
#define FLASH_SMEM (FQSZ2 + 2 * FSTAGE) // 212992
#define NKVT   (SEQ / 64)               // 32

__device__ __forceinline__ void flash_load_stage(
    uint32_t sbase, int tid, int j,
    const __nv_bfloat16* Kh, const __nv_bfloat16* Kl,
    const __nv_bfloat16* VTh, const __nv_bfloat16* VTl)
{
    const uint32_t st = sbase + FQSZ2 + (j & 1) * FSTAGE;
    const int kv0 = j * 64;
#pragma unroll
    for (int w = 0; w < 4; w++) {           // K: 64 rows x 16 chunks
        int chunk = tid + w * 256;
        int row = chunk >> 4;
        int c   = chunk & 15;
        size_t go = (size_t)(kv0 + row) * DK + c * 8;
        cp16(st + row * FQROW + c * 16, Kh + go);
        cp16(st + FKSZ + row * FQROW + c * 16, Kl + go);
    }
#pragma unroll
    for (int w = 0; w < 4; w++) {           // VT: 128 rows x 8 chunks
        int chunk = tid + w * 256;
        int row = chunk >> 3;
        int c   = chunk & 7;
        size_t go = (size_t)row * SEQ + kv0 + c * 8;
        cp16(st + 2 * FKSZ + row * FVROW + c * 16, VTh + go);
        cp16(st + 2 * FKSZ + FVSZ + row * FVROW + c * 16, VTl + go);
    }
    CP_COMMIT();
}

__global__ void __launch_bounds__(256)
flash_mma_kernel(const __nv_bfloat16* __restrict__ Qhi, const __nv_bfloat16* __restrict__ Qlo,
                 const __nv_bfloat16* __restrict__ Khi, const __nv_bfloat16* __restrict__ Klo,
                 const __nv_bfloat16* __restrict__ VThi, const __nv_bfloat16* __restrict__ VTlo,
                 float* __restrict__ CTX)
{
    extern __shared__ __align__(16) char smem[];
    uint32_t sbase = smem_u32(smem);
    const int tid  = threadIdx.x;
    const int wid  = tid >> 5;
    const int lane = tid & 31;
    const int g    = lane >> 2;
    const int t4   = lane & 3;
    const int wm   = wid * 16;
    const int bh = blockIdx.y;
    const int q0 = blockIdx.x * 128;

    const __nv_bfloat16* Qh = Qhi + ((size_t)bh * SEQ + q0) * DK;
    const __nv_bfloat16* Ql = Qlo + ((size_t)bh * SEQ + q0) * DK;
    const __nv_bfloat16* Kh = Khi + (size_t)bh * SEQ * DK;
    const __nv_bfloat16* Kl = Klo + (size_t)bh * SEQ * DK;
    const __nv_bfloat16* Vh = VThi + (size_t)bh * DK * SEQ;
    const __nv_bfloat16* Vl = VTlo + (size_t)bh * DK * SEQ;

    // Q tile loads (hi+lo) + stage 0 in group 0
#pragma unroll
    for (int w = 0; w < 8; w++) {
        int chunk = tid + w * 256;
        int row = chunk >> 4;
        int c   = chunk & 15;
        size_t go = (size_t)row * DK + c * 8;
        cp16(sbase + row * FQROW + c * 16, Qh + go);
        cp16(sbase + FQSZ + row * FQROW + c * 16, Ql + go);
    }
    flash_load_stage(sbase, tid, 0, Kh, Kl, Vh, Vl);   // commits group 0 (incl. Q)
    flash_load_stage(sbase, tid, 1, Kh, Kl, Vh, Vl);   // group 1

    float m0 = -INFINITY, m1 = -INFINITY, l0 = 0.0f, l1 = 0.0f;
    float oacc[16][4];
#pragma unroll
    for (int i = 0; i < 16; i++)
#pragma unroll
        for (int r = 0; r < 4; r++) oacc[i][r] = 0.0f;

    for (int j = 0; j < NKVT; j++) {
        if (j == NKVT - 1) { CP_WAIT(0); } else { CP_WAIT(1); }
        __syncthreads();
        const uint32_t st = sbase + FQSZ2 + (j & 1) * FSTAGE;

        // ---- QK: S[16 x 64] per warp, 3 products ----
        float sacc[8][4];
#pragma unroll
        for (int nb = 0; nb < 8; nb++)
#pragma unroll
            for (int r = 0; r < 4; r++) sacc[nb][r] = 0.0f;

#pragma unroll
        for (int kb = 0; kb < 8; kb++) {
            const uint32_t ko = kb * 32 + t4 * 4;
            uint32_t qh[4], ql[4];
            {
                uint32_t r = sbase + (wm + g) * FQROW + ko;
                qh[0] = lds32(r);
                qh[1] = lds32(r + 8 * FQROW);
                qh[2] = lds32(r + 16);
                qh[3] = lds32(r + 8 * FQROW + 16);
                uint32_t rl = r + FQSZ;
                ql[0] = lds32(rl);
                ql[1] = lds32(rl + 8 * FQROW);
                ql[2] = lds32(rl + 16);
                ql[3] = lds32(rl + 8 * FQROW + 16);
            }
#pragma unroll
            for (int nb = 0; nb < 8; nb++) {
                uint32_t kr = st + (nb * 8 + g) * FQROW + ko;
                uint32_t bhF[2], blF[2];
                bhF[0] = lds32(kr);
                bhF[1] = lds32(kr + 16);
                blF[0] = lds32(kr + FKSZ);
                blF[1] = lds32(kr + FKSZ + 16);
                MMA16816(sacc[nb], qh, bhF);
                MMA16816(sacc[nb], qh, blF);
                MMA16816(sacc[nb], ql, bhF);
            }
        }

        // ---- online softmax ----
        float mx0 = -INFINITY, mx1 = -INFINITY;
#pragma unroll
        for (int nb = 0; nb < 8; nb++) {
#pragma unroll
            for (int r = 0; r < 4; r++) sacc[nb][r] *= SM_SCALE;
            mx0 = fmaxf(mx0, fmaxf(sacc[nb][0], sacc[nb][1]));
            mx1 = fmaxf(mx1, fmaxf(sacc[nb][2], sacc[nb][3]));
        }
        mx0 = fmaxf(mx0, __shfl_xor_sync(0xffffffffu, mx0, 1));
        mx0 = fmaxf(mx0, __shfl_xor_sync(0xffffffffu, mx0, 2));
        mx1 = fmaxf(mx1, __shfl_xor_sync(0xffffffffu, mx1, 1));
        mx1 = fmaxf(mx1, __shfl_xor_sync(0xffffffffu, mx1, 2));

        float mn0 = fmaxf(m0, mx0), mn1 = fmaxf(m1, mx1);
        float sc0 = __expf(m0 - mn0), sc1 = __expf(m1 - mn1);
        m0 = mn0; m1 = mn1;

        float rs0 = 0.0f, rs1 = 0.0f;
#pragma unroll
        for (int nb = 0; nb < 8; nb++) {
            float p0 = __expf(sacc[nb][0] - mn0);
            float p1 = __expf(sacc[nb][1] - mn0);
            float p2 = __expf(sacc[nb][2] - mn1);
            float p3 = __expf(sacc[nb][3] - mn1);
            sacc[nb][0] = p0; sacc[nb][1] = p1; sacc[nb][2] = p2; sacc[nb][3] = p3;
            rs0 += p0 + p1; rs1 += p2 + p3;
        }
        rs0 += __shfl_xor_sync(0xffffffffu, rs0, 1);
        rs0 += __shfl_xor_sync(0xffffffffu, rs0, 2);
        rs1 += __shfl_xor_sync(0xffffffffu, rs1, 1);
        rs1 += __shfl_xor_sync(0xffffffffu, rs1, 2);
        l0 = l0 * sc0 + rs0;
        l1 = l1 * sc1 + rs1;

#pragma unroll
        for (int nb = 0; nb < 16; nb++) {
            oacc[nb][0] *= sc0; oacc[nb][1] *= sc0;
            oacc[nb][2] *= sc1; oacc[nb][3] *= sc1;
        }

        // ---- pack P into A-fragments (hi/lo) ----
        uint32_t ph[4][4], pl[4][4];
#pragma unroll
        for (int kb = 0; kb < 4; kb++) {
            split2(sacc[2 * kb][0],     sacc[2 * kb][1],     ph[kb][0], pl[kb][0]);
            split2(sacc[2 * kb][2],     sacc[2 * kb][3],     ph[kb][1], pl[kb][1]);
            split2(sacc[2 * kb + 1][0], sacc[2 * kb + 1][1], ph[kb][2], pl[kb][2]);
            split2(sacc[2 * kb + 1][2], sacc[2 * kb + 1][3], ph[kb][3], pl[kb][3]);
        }

        // ---- PV: O[16 x 128] += P[16 x 64] @ V[64 x 128] (3 products) ----
        const uint32_t vb = st + 2 * FKSZ;
#pragma unroll
        for (int kb = 0; kb < 4; kb++) {
#pragma unroll
            for (int nb = 0; nb < 16; nb++) {
                uint32_t vr = vb + (nb * 8 + g) * FVROW + kb * 32 + t4 * 4;
                uint32_t bhF[2], blF[2];
                bhF[0] = lds32(vr);
                bhF[1] = lds32(vr + 16);
                blF[0] = lds32(vr + FVSZ);
                blF[1] = lds32(vr + FVSZ + 16);
                MMA16816(oacc[nb], ph[kb], bhF);
                MMA16816(oacc[nb], ph[kb], blF);
                MMA16816(oacc[nb], pl[kb], bhF);
            }
        }

        __syncthreads();
        if (j + 2 < NKVT)
            flash_load_stage(sbase, tid, j + 2, Kh, Kl, Vh, Vl);
    }

    // ---- write ctx [b*S+s][h*128+d] ----
    const int b = bh >> 4;
    const int h = bh & 15;
    const float inv0 = 1.0f / l0;
    const float inv1 = 1.0f / l1;
    const int s0r = q0 + wm + g;
    float* o0 = &CTX[((size_t)(b * SEQ + s0r)) * DMODEL + h * DK];
    float* o1 = &CTX[((size_t)(b * SEQ + s0r + 8)) * DMODEL + h * DK];
#pragma unroll
    for (int nb = 0; nb < 16; nb++) {
        int d = nb * 8 + t4 * 2;
        *(float2*)&o0[d] = make_float2(oacc[nb][0] * inv0, oacc[nb][1] * inv0);
        *(float2*)&o1[d] = make_float2(oacc[nb][2] * inv1, oacc[nb][3] * inv1);
    }
}

// ---------------------------------------------------------------------------
// Launch
// ---------------------------------------------------------------------------
extern "C" void kernel_launch(void* const* d_in, const int* in_sizes, int n_in,
                              void* d_out, int out_size)
{
    const float* x  = (const float*)d_in[0];
    const float* Wq = (const float*)d_in[1];
    const float* bq = (const float*)d_in[2];
    const float* Aq = (const float*)d_in[3];
    const float* Bq = (const float*)d_in[4];
    const float* Wk = (const float*)d_in[5];
    const float* bk = (const float*)d_in[6];
    const float* Ak = (const float*)d_in[7];
    const float* Bk = (const float*)d_in[8];
    const float* Wv = (const float*)d_in[9];
    const float* bv = (const float*)d_in[10];
    const float* Av = (const float*)d_in[11];
    const float* Bv = (const float*)d_in[12];
    const float* Wo = (const float*)d_in[13];
    const float* bo = (const float*)d_in[14];
    const float* Ao = (const float*)d_in[15];
    const float* Bo = (const float*)d_in[16];
    float* out = (float*)d_out;

    float *pt, *pto, *pctx;
    __nv_bfloat16 *pxhi, *pxlo, *pwhi, *pwlo, *pchi, *pclo;
    __nv_bfloat16 *pqhi, *pqlo, *pkhi, *pklo, *pvhi, *pvlo, *pvthi, *pvtlo;
    cudaGetSymbolAddress((void**)&pt,   g_t_qkv);
    cudaGetSymbolAddress((void**)&pto,  g_t_o);
    cudaGetSymbolAddress((void**)&pctx, g_ctx);
    cudaGetSymbolAddress((void**)&pxhi, g_xhi);
    cudaGetSymbolAddress((void**)&pxlo, g_xlo);
    cudaGetSymbolAddress((void**)&pwhi, g_whi);
    cudaGetSymbolAddress((void**)&pwlo, g_wlo);
    cudaGetSymbolAddress((void**)&pchi, g_chi);
    cudaGetSymbolAddress((void**)&pclo, g_clo);
    cudaGetSymbolAddress((void**)&pqhi, g_qhi);
    cudaGetSymbolAddress((void**)&pqlo, g_qlo);
    cudaGetSymbolAddress((void**)&pkhi, g_khi);
    cudaGetSymbolAddress((void**)&pklo, g_klo);
    cudaGetSymbolAddress((void**)&pvhi, g_vhi);
    cudaGetSymbolAddress((void**)&pvlo, g_vlo);
    cudaGetSymbolAddress((void**)&pvthi, g_vthi);
    cudaGetSymbolAddress((void**)&pvtlo, g_vtlo);

    cudaFuncSetAttribute(gemm_mma_kernel<0>,
                         cudaFuncAttributeMaxDynamicSharedMemorySize, GEMM_SMEM);
    cudaFuncSetAttribute(gemm_mma_kernel<1>,
                         cudaFuncAttributeMaxDynamicSharedMemorySize, GEMM_SMEM);
    cudaFuncSetAttribute(flash_mma_kernel,
                         cudaFuncAttributeMaxDynamicSharedMemorySize, FLASH_SMEM);

    const size_t WSZ = (size_t)DMODEL * DMODEL;
    const int nX4 = MTOT * DMODEL / 4;
    const int nW4 = (int)(WSZ / 4);
    const int sg  = 256;

    // 1) Splits
    split_kernel<<<(nX4 + sg - 1) / sg, sg>>>(x, pxhi, pxlo, nX4);
    split_kernel<<<(nW4 + sg - 1) / sg, sg>>>(Wq, pwhi + 0 * WSZ, pwlo + 0 * WSZ, nW4);
    split_kernel<<<(nW4 + sg - 1) / sg, sg>>>(Wk, pwhi + 1 * WSZ, pwlo + 1 * WSZ, nW4);
    split_kernel<<<(nW4 + sg - 1) / sg, sg>>>(Wv, pwhi + 2 * WSZ, pwlo + 2 * WSZ, nW4);
    split_kernel<<<(nW4 + sg - 1) / sg, sg>>>(Wo, pwhi + 3 * WSZ, pwlo + 3 * WSZ, nW4);

    // 2) LoRA intermediates
    lora_t_kernel<3><<<MTOT, 256>>>(x, Aq, Ak, Av, pt, 24);

    // 3) Projections -> bf16 hi/lo head-major
    dim3 ggrid(DMODEL / 128, MTOT / 128);
    gemm_mma_kernel<1><<<ggrid, 256, GEMM_SMEM>>>(pxhi, pxlo, pwhi + 0 * WSZ, pwlo + 0 * WSZ,
                                                  bq, pt, Bq, nullptr, pqhi, pqlo, 24, 0);
    gemm_mma_kernel<1><<<ggrid, 256, GEMM_SMEM>>>(pxhi, pxlo, pwhi + 1 * WSZ, pwlo + 1 * WSZ,
                                                  bk, pt, Bk, nullptr, pkhi, pklo, 24, 8);
    gemm_mma_kernel<1><<<ggrid, 256, GEMM_SMEM>>>(pxhi, pxlo, pwhi + 2 * WSZ, pwlo + 2 * WSZ,
                                                  bv, pt, Bv, nullptr, pvhi, pvlo, 24, 16);

    // 4) V transpose
    dim3 tgrid(SEQ / 64, DK / 64, NBH);
    vtrans_kernel<<<tgrid, 256>>>(pvhi, pvlo, pvthi, pvtlo);

    // 5) Flash attention (tensor core)
    dim3 fgrid(SEQ / 128, NBH);
    flash_mma_kernel<<<fgrid, 256, FLASH_SMEM>>>(pqhi, pqlo, pkhi, pklo, pvthi, pvtlo, pctx);

    // 6) Output projection
    split_kernel<<<(nX4 + sg - 1) / sg, sg>>>(pctx, pchi, pclo, nX4);
    lora_t_kernel<1><<<MTOT, 256>>>(pctx, Ao, Ao, Ao, pto, 8);
    gemm_mma_kernel<0><<<ggrid, 256, GEMM_SMEM>>>(pchi, pclo, pwhi + 3 * WSZ, pwlo + 3 * WSZ,
                                                  bo, pto, Bo, out, nullptr, nullptr, 8, 0);
}